// round 6
// baseline (speedup 1.0000x reference)
#include <cuda_runtime.h>
#include <cuda_fp16.h>
#include <cstdint>
#include <cstddef>

// Problem constants
#define TOKENS 32768      // 8 * 4096
#define DIN    1024
#define RNK    64
#define NE     8
#define N72    72         // NE + RNK
#define DOUT   1024
#define KMID   512        // NE * RNK
#define SCALING 0.25f     // alpha / r = 16/64

// ---------------------------------------------------------------------------
// Scratch (device globals; no runtime allocation allowed)
// ---------------------------------------------------------------------------
__device__ __half g_W72h[N72 * DIN];             // [72][1024] fp16
__device__ __half g_Wt[DOUT * KMID];             // [o][k]: Wt[o][e*64+r] = B[e][o][r]
__device__ __half g_Dh[(size_t)TOKENS * KMID];   // 32 MiB: D[t][e*64+r] fp16

// ---------------------------------------------------------------------------
// Helpers
// ---------------------------------------------------------------------------
__device__ __forceinline__ void mma16(float c[4], const unsigned a[4],
                                      unsigned b0, unsigned b1) {
    asm volatile(
        "mma.sync.aligned.m16n8k16.row.col.f32.f16.f16.f32 "
        "{%0,%1,%2,%3}, {%4,%5,%6,%7}, {%8,%9}, {%0,%1,%2,%3};\n"
        : "+f"(c[0]), "+f"(c[1]), "+f"(c[2]), "+f"(c[3])
        : "r"(a[0]), "r"(a[1]), "r"(a[2]), "r"(a[3]), "r"(b0), "r"(b1));
}

__device__ __forceinline__ void cp16(void* smem, const void* gmem) {
    unsigned saddr = (unsigned)__cvta_generic_to_shared(smem);
    asm volatile("cp.async.cg.shared.global [%0], [%1], 16;\n"
                 :: "r"(saddr), "l"(gmem));
}

__device__ __forceinline__ uint32_t smem_u32(const void* p) {
    return (uint32_t)__cvta_generic_to_shared(p);
}

__device__ __forceinline__ void ldsm4(unsigned& r0, unsigned& r1,
                                      unsigned& r2, unsigned& r3,
                                      uint32_t addr) {
    asm volatile("ldmatrix.sync.aligned.m8n8.x4.shared.b16 "
                 "{%0,%1,%2,%3}, [%4];"
                 : "=r"(r0), "=r"(r1), "=r"(r2), "=r"(r3) : "r"(addr));
}

// ---------------------------------------------------------------------------
// K0: prep weights (fp16)
// ---------------------------------------------------------------------------
__global__ void k0_prep(const float* __restrict__ route_w,
                        const float* __restrict__ A,
                        const float* __restrict__ B) {
    int idx = blockIdx.x * 256 + threadIdx.x;
    if (idx < N72 * DIN) {
        int n = idx / DIN, d = idx % DIN;
        float v = (n < NE) ? route_w[n * DIN + d] : A[(n - NE) * DIN + d];
        g_W72h[idx] = __float2half_rn(v);
    }
    int j = idx - N72 * DIN;
    if (j >= 0 && j < DOUT * KMID) {
        int o = j / KMID, k = j % KMID;
        int e = k >> 6, r = k & 63;
        g_Wt[j] = __float2half_rn(B[(e * DOUT + o) * RNK + r]);
    }
}

// ---------------------------------------------------------------------------
// K1: fused router+compress (fp16 mma) -> softmax -> outer -> D (fp16)
// ---------------------------------------------------------------------------
__global__ __launch_bounds__(256) void k1_fused(const float* __restrict__ X) {
    __shared__ float shf[9728];              // 38912 B, reused for Cs
    unsigned* Xs = (unsigned*)shf;           // [128][36] words
    unsigned* Ws = (unsigned*)shf + 128 * 36;// [72][36] words

    int tid = threadIdx.x, warp = tid >> 5, lane = tid & 31;
    int m0 = blockIdx.x * 128;

    float acc[9][4] = {};

    float4 xr[8];
    uint4  wr[3];

    auto loadg = [&](int kt) {
        #pragma unroll
        for (int i = 0; i < 8; i++) {
            int idx = tid + i * 256;
            int r = idx >> 4, c4 = idx & 15;
            xr[i] = *(const float4*)(X + (size_t)(m0 + r) * DIN + kt + c4 * 4);
        }
        #pragma unroll
        for (int i = 0; i < 3; i++) {
            int idx = tid + i * 256;
            if (idx < 576) {
                int r = idx >> 3, c = idx & 7;
                wr[i] = *(const uint4*)((const char*)(g_W72h + r * DIN + kt) + c * 16);
            }
        }
    };

    loadg(0);

    for (int kt = 0; kt < 16; kt++) {
        #pragma unroll
        for (int i = 0; i < 8; i++) {
            int idx = tid + i * 256;
            int r = idx >> 4, c4 = idx & 15;
            __half2* dst = (__half2*)(Xs + r * 36 + c4 * 2);
            dst[0] = __floats2half2_rn(xr[i].x, xr[i].y);
            dst[1] = __floats2half2_rn(xr[i].z, xr[i].w);
        }
        #pragma unroll
        for (int i = 0; i < 3; i++) {
            int idx = tid + i * 256;
            if (idx < 576) {
                int r = idx >> 3, c = idx & 7;
                *(uint4*)(Ws + r * 36 + c * 4) = wr[i];
            }
        }
        __syncthreads();

        if (kt + 1 < 16) loadg((kt + 1) * 64);   // gmem loads overlap MMA below

        #pragma unroll
        for (int s = 0; s < 4; s++) {       // 4 x k16
            unsigned a[4];
            int ar = warp * 16 + (lane >> 2);
            int w = s * 8 + (lane & 3);
            a[0] = Xs[ar * 36 + w];
            a[1] = Xs[(ar + 8) * 36 + w];
            a[2] = Xs[ar * 36 + w + 4];
            a[3] = Xs[(ar + 8) * 36 + w + 4];
            #pragma unroll
            for (int j = 0; j < 9; j++) {
                int br = j * 8 + (lane >> 2);
                unsigned b0 = Ws[br * 36 + w];
                unsigned b1 = Ws[br * 36 + w + 4];
                mma16(acc[j], a, b0, b1);
            }
        }
        __syncthreads();
    }

    // stage C72 into smem: Cs[128][76]
    float* Cs = shf;
    #pragma unroll
    for (int j = 0; j < 9; j++) {
        int col = j * 8 + 2 * (lane & 3);
        int row = warp * 16 + (lane >> 2);
        Cs[row * 76 + col]           = acc[j][0];
        Cs[row * 76 + col + 1]       = acc[j][1];
        Cs[(row + 8) * 76 + col]     = acc[j][2];
        Cs[(row + 8) * 76 + col + 1] = acc[j][3];
    }
    __syncthreads();

    // softmax + outer product; 8-thread groups, 4 tokens each
    int grp = tid >> 3, g = tid & 7;
    #pragma unroll
    for (int tt = 0; tt < 4; tt++) {
        int lt = grp + tt * 32;
        const float* crow = Cs + lt * 76;
        float mx = crow[0];
        #pragma unroll
        for (int e = 1; e < 8; e++) mx = fmaxf(mx, crow[e]);
        float p[8]; float se = 0.f;
        #pragma unroll
        for (int e = 0; e < 8; e++) { p[e] = expf(crow[e] - mx); se += p[e]; }
        float inv = 1.f / se;
        __half* drow = g_Dh + (size_t)(m0 + lt) * KMID;
        #pragma unroll
        for (int e = 0; e < 8; e++) {
            float route = p[e] * inv;
            #pragma unroll
            for (int h = 0; h < 2; h++) {
                int r = (g + h * 8) * 4;
                float4 cv = *(const float4*)(crow + 8 + r);
                __half2 h0 = __floats2half2_rn(route * cv.x, route * cv.y);
                __half2 h1 = __floats2half2_rn(route * cv.z, route * cv.w);
                *(__half2*)(drow + e * 64 + r)     = h0;
                *(__half2*)(drow + e * 64 + r + 2) = h1;
            }
        }
    }
}

// ---------------------------------------------------------------------------
// K3: GEMM2: Y = (D @ Wt^T) * SCALING, fp16 mma fp32 accum.
//   M=32768 N=1024 K=512. Block 256x256, K-tile 64 halves, 3-stage cp.async
//   ring, ldmatrix. 16 warps in 4x4, warp tile 64x64.
// ---------------------------------------------------------------------------
#define BM 256
#define BN 256
#define NKT 8                               // 512 / 64
#define STG_W (BM * 36)                     // words per matrix per stage (A; B same)
#define K3_STAGES 3
#define K3_SMEM (K3_STAGES * 2 * STG_W * 4) // 221184 B

__global__ __launch_bounds__(512, 1) void k3_gemm(float* __restrict__ Y) {
    extern __shared__ unsigned sh[];
    int tid = threadIdx.x, warp = tid >> 5, lane = tid & 31;
    int wm = warp >> 2, wn = warp & 3;
    int m0 = blockIdx.x * BM, n0 = blockIdx.y * BN;

    float acc[4][8][4] = {};                 // mt x (np*2+half) x 4

    unsigned* stA[K3_STAGES];
    unsigned* stB[K3_STAGES];
    #pragma unroll
    for (int s = 0; s < K3_STAGES; s++) {
        stA[s] = sh + s * (2 * STG_W);
        stB[s] = sh + s * (2 * STG_W) + STG_W;
    }

    // ldmatrix lane-relative offsets (bytes)
    int g4 = lane >> 3, lr = lane & 7;
    uint32_t relA[4], relB[4];
    {
        int rowSel = (g4 & 1) * 8 + lr;
        int wordSel = (g4 >> 1) * 4;
        #pragma unroll
        for (int mt = 0; mt < 4; mt++)
            relA[mt] = ((wm * 64 + mt * 16 + rowSel) * 36 + wordSel) * 4;
        int browSel = (g4 >> 1) * 8 + lr;
        int bwordSel = (g4 & 1) * 4;
        #pragma unroll
        for (int np = 0; np < 4; np++)
            relB[np] = ((wn * 64 + np * 16 + browSel) * 36 + bwordSel) * 4;
    }
    uint32_t uA[K3_STAGES], uB[K3_STAGES];
    #pragma unroll
    for (int s = 0; s < K3_STAGES; s++) {
        uA[s] = smem_u32(stA[s]);
        uB[s] = smem_u32(stB[s]);
    }

    auto prefetch = [&](int st, int kt) {
        unsigned* As = stA[st];
        unsigned* Bs = stB[st];
        const __half* gA = g_Dh + (size_t)m0 * KMID + kt * 64;
        const __half* gB = g_Wt + (size_t)n0 * KMID + kt * 64;
        #pragma unroll
        for (int i = 0; i < 8; i++) {
            int idx = tid + i * 512;        // 0..4095
            int which = idx >> 11;
            int j = idx & 2047;
            int r = j >> 3, c = j & 7;      // 8 x 16B chunks per 128B row
            if (which == 0)
                cp16(As + r * 36 + c * 4, (const char*)(gA + (size_t)r * KMID) + c * 16);
            else
                cp16(Bs + r * 36 + c * 4, (const char*)(gB + (size_t)r * KMID) + c * 16);
        }
        asm volatile("cp.async.commit_group;\n" ::: "memory");
    };

    prefetch(0, 0);
    prefetch(1, 1);

    for (int kt = 0; kt < NKT; kt++) {
        int st = kt % K3_STAGES;
        if (kt + 2 < NKT) {
            prefetch((kt + 2) % K3_STAGES, kt + 2);
            asm volatile("cp.async.wait_group 2;\n" ::: "memory");
        } else if (kt + 1 < NKT) {
            asm volatile("cp.async.wait_group 1;\n" ::: "memory");
        } else {
            asm volatile("cp.async.wait_group 0;\n" ::: "memory");
        }
        __syncthreads();

        #pragma unroll
        for (int s = 0; s < 4; s++) {       // 4 x k16 per tile
            unsigned a[4][4], b[4][4];
            #pragma unroll
            for (int mt = 0; mt < 4; mt++)
                ldsm4(a[mt][0], a[mt][1], a[mt][2], a[mt][3],
                      uA[st] + relA[mt] + s * 32);
            #pragma unroll
            for (int np = 0; np < 4; np++)
                ldsm4(b[np][0], b[np][1], b[np][2], b[np][3],
                      uB[st] + relB[np] + s * 32);
            #pragma unroll
            for (int mt = 0; mt < 4; mt++) {
                #pragma unroll
                for (int np = 0; np < 4; np++) {
                    mma16(acc[mt][np * 2],     a[mt], b[np][0], b[np][1]);
                    mma16(acc[mt][np * 2 + 1], a[mt], b[np][2], b[np][3]);
                }
            }
        }
        __syncthreads();
    }

    // epilogue: scale + store
    #pragma unroll
    for (int mt = 0; mt < 4; mt++) {
        #pragma unroll
        for (int nf = 0; nf < 8; nf++) {
            int row = m0 + wm * 64 + mt * 16 + (lane >> 2);
            int col = n0 + wn * 64 + nf * 8 + 2 * (lane & 3);
            float2 v0 = make_float2(acc[mt][nf][0] * SCALING,
                                    acc[mt][nf][1] * SCALING);
            float2 v1 = make_float2(acc[mt][nf][2] * SCALING,
                                    acc[mt][nf][3] * SCALING);
            *(float2*)(Y + (size_t)row * DOUT + col)       = v0;
            *(float2*)(Y + (size_t)(row + 8) * DOUT + col) = v1;
        }
    }
}

// ---------------------------------------------------------------------------
// Launch
// ---------------------------------------------------------------------------
extern "C" void kernel_launch(void* const* d_in, const int* in_sizes, int n_in,
                              void* d_out, int out_size) {
    (void)in_sizes; (void)n_in; (void)out_size;
    const float* x       = (const float*)d_in[0];
    const float* route_w = (const float*)d_in[1];
    const float* A       = (const float*)d_in[2];
    const float* B       = (const float*)d_in[3];
    float* y = (float*)d_out;

    cudaFuncSetAttribute(k3_gemm, cudaFuncAttributeMaxDynamicSharedMemorySize,
                         K3_SMEM);

    int prep_elems = N72 * DIN + DOUT * KMID;
    k0_prep<<<(prep_elems + 255) / 256, 256>>>(route_w, A, B);
    k1_fused<<<TOKENS / 128, 256>>>(x);
    dim3 g3(TOKENS / BM, DOUT / BN);
    k3_gemm<<<g3, 512, K3_SMEM>>>(y);
}

// round 7
// speedup vs baseline: 2.4457x; 2.4457x over previous
#include <cuda_runtime.h>
#include <cuda_fp16.h>
#include <cstdint>
#include <cstddef>

// Problem constants
#define TOKENS 32768      // 8 * 4096
#define DIN    1024
#define RNK    64
#define NE     8
#define N72    72         // NE + RNK
#define DOUT   1024
#define KMID   512        // NE * RNK
#define SCALING 0.25f     // alpha / r = 16/64

// ---------------------------------------------------------------------------
// Scratch (device globals; no runtime allocation allowed)
// ---------------------------------------------------------------------------
__device__ __half g_W72h[N72 * DIN];             // [72][1024] fp16
__device__ __half g_Wt[DOUT * KMID];             // [o][k]: Wt[o][e*64+r] = B[e][o][r]
__device__ __half g_Dh[(size_t)TOKENS * KMID];   // 32 MiB: D[t][e*64+r] fp16

// ---------------------------------------------------------------------------
// Helpers
// ---------------------------------------------------------------------------
__device__ __forceinline__ void mma16(float c[4], const unsigned a[4],
                                      unsigned b0, unsigned b1) {
    asm volatile(
        "mma.sync.aligned.m16n8k16.row.col.f32.f16.f16.f32 "
        "{%0,%1,%2,%3}, {%4,%5,%6,%7}, {%8,%9}, {%0,%1,%2,%3};\n"
        : "+f"(c[0]), "+f"(c[1]), "+f"(c[2]), "+f"(c[3])
        : "r"(a[0]), "r"(a[1]), "r"(a[2]), "r"(a[3]), "r"(b0), "r"(b1));
}

__device__ __forceinline__ void cp16(void* smem, const void* gmem) {
    unsigned saddr = (unsigned)__cvta_generic_to_shared(smem);
    asm volatile("cp.async.cg.shared.global [%0], [%1], 16;\n"
                 :: "r"(saddr), "l"(gmem));
}

__device__ __forceinline__ uint32_t smem_u32(const void* p) {
    return (uint32_t)__cvta_generic_to_shared(p);
}

__device__ __forceinline__ void ldsm4(unsigned& r0, unsigned& r1,
                                      unsigned& r2, unsigned& r3,
                                      uint32_t addr) {
    asm volatile("ldmatrix.sync.aligned.m8n8.x4.shared.b16 "
                 "{%0,%1,%2,%3}, [%4];"
                 : "=r"(r0), "=r"(r1), "=r"(r2), "=r"(r3) : "r"(addr));
}

// ---------------------------------------------------------------------------
// K0: prep weights (fp16)
// ---------------------------------------------------------------------------
__global__ void k0_prep(const float* __restrict__ route_w,
                        const float* __restrict__ A,
                        const float* __restrict__ B) {
    int idx = blockIdx.x * 256 + threadIdx.x;
    if (idx < N72 * DIN) {
        int n = idx / DIN, d = idx % DIN;
        float v = (n < NE) ? route_w[n * DIN + d] : A[(n - NE) * DIN + d];
        g_W72h[idx] = __float2half_rn(v);
    }
    int j = idx - N72 * DIN;
    if (j >= 0 && j < DOUT * KMID) {
        int o = j / KMID, k = j % KMID;
        int e = k >> 6, r = k & 63;
        g_Wt[j] = __float2half_rn(B[(e * DOUT + o) * RNK + r]);
    }
}

// ---------------------------------------------------------------------------
// K1: fused router+compress (fp16 mma) -> softmax -> outer -> D (fp16)
// ---------------------------------------------------------------------------
__global__ __launch_bounds__(256) void k1_fused(const float* __restrict__ X) {
    __shared__ float shf[9728];              // 38912 B, reused for Cs
    unsigned* Xs = (unsigned*)shf;           // [128][36] words
    unsigned* Ws = (unsigned*)shf + 128 * 36;// [72][36] words

    int tid = threadIdx.x, warp = tid >> 5, lane = tid & 31;
    int m0 = blockIdx.x * 128;

    float acc[9][4] = {};

    float4 xr[8];
    uint4  wr[3];

    auto loadg = [&](int kt) {
        #pragma unroll
        for (int i = 0; i < 8; i++) {
            int idx = tid + i * 256;
            int r = idx >> 4, c4 = idx & 15;
            xr[i] = *(const float4*)(X + (size_t)(m0 + r) * DIN + kt + c4 * 4);
        }
        #pragma unroll
        for (int i = 0; i < 3; i++) {
            int idx = tid + i * 256;
            if (idx < 576) {
                int r = idx >> 3, c = idx & 7;
                wr[i] = *(const uint4*)((const char*)(g_W72h + r * DIN + kt) + c * 16);
            }
        }
    };

    loadg(0);

    for (int kt = 0; kt < 16; kt++) {
        #pragma unroll
        for (int i = 0; i < 8; i++) {
            int idx = tid + i * 256;
            int r = idx >> 4, c4 = idx & 15;
            __half2* dst = (__half2*)(Xs + r * 36 + c4 * 2);
            dst[0] = __floats2half2_rn(xr[i].x, xr[i].y);
            dst[1] = __floats2half2_rn(xr[i].z, xr[i].w);
        }
        #pragma unroll
        for (int i = 0; i < 3; i++) {
            int idx = tid + i * 256;
            if (idx < 576) {
                int r = idx >> 3, c = idx & 7;
                *(uint4*)(Ws + r * 36 + c * 4) = wr[i];
            }
        }
        __syncthreads();

        if (kt + 1 < 16) loadg((kt + 1) * 64);   // gmem loads overlap MMA below

        #pragma unroll
        for (int s = 0; s < 4; s++) {       // 4 x k16
            unsigned a[4];
            int ar = warp * 16 + (lane >> 2);
            int w = s * 8 + (lane & 3);
            a[0] = Xs[ar * 36 + w];
            a[1] = Xs[(ar + 8) * 36 + w];
            a[2] = Xs[ar * 36 + w + 4];
            a[3] = Xs[(ar + 8) * 36 + w + 4];
            #pragma unroll
            for (int j = 0; j < 9; j++) {
                int br = j * 8 + (lane >> 2);
                unsigned b0 = Ws[br * 36 + w];
                unsigned b1 = Ws[br * 36 + w + 4];
                mma16(acc[j], a, b0, b1);
            }
        }
        __syncthreads();
    }

    // stage C72 into smem: Cs[128][76]
    float* Cs = shf;
    #pragma unroll
    for (int j = 0; j < 9; j++) {
        int col = j * 8 + 2 * (lane & 3);
        int row = warp * 16 + (lane >> 2);
        Cs[row * 76 + col]           = acc[j][0];
        Cs[row * 76 + col + 1]       = acc[j][1];
        Cs[(row + 8) * 76 + col]     = acc[j][2];
        Cs[(row + 8) * 76 + col + 1] = acc[j][3];
    }
    __syncthreads();

    // softmax + outer product; 8-thread groups, 4 tokens each
    int grp = tid >> 3, g = tid & 7;
    #pragma unroll
    for (int tt = 0; tt < 4; tt++) {
        int lt = grp + tt * 32;
        const float* crow = Cs + lt * 76;
        float mx = crow[0];
        #pragma unroll
        for (int e = 1; e < 8; e++) mx = fmaxf(mx, crow[e]);
        float p[8]; float se = 0.f;
        #pragma unroll
        for (int e = 0; e < 8; e++) { p[e] = expf(crow[e] - mx); se += p[e]; }
        float inv = 1.f / se;
        __half* drow = g_Dh + (size_t)(m0 + lt) * KMID;
        #pragma unroll
        for (int e = 0; e < 8; e++) {
            float route = p[e] * inv;
            #pragma unroll
            for (int h = 0; h < 2; h++) {
                int r = (g + h * 8) * 4;
                float4 cv = *(const float4*)(crow + 8 + r);
                __half2 h0 = __floats2half2_rn(route * cv.x, route * cv.y);
                __half2 h1 = __floats2half2_rn(route * cv.z, route * cv.w);
                *(__half2*)(drow + e * 64 + r)     = h0;
                *(__half2*)(drow + e * 64 + r + 2) = h1;
            }
        }
    }
}

// ---------------------------------------------------------------------------
// K3: GEMM2: Y = (D @ Wt^T) * SCALING, fp16 mma fp32 accum.
//   M=32768 N=1024 K=512. Block 128x256, 256 threads (8 warps 2x4),
//   warp tile 64x64, K-tile 64 halves, 3-stage cp.async ring, ldmatrix.
// ---------------------------------------------------------------------------
#define BM 128
#define BN 256
#define NKT 8                               // 512 / 64
#define STG_WA (BM * 36)                    // A words per stage
#define STG_WB (BN * 36)                    // B words per stage
#define STG_W  (STG_WA + STG_WB)
#define K3_STAGES 3
#define K3_SMEM (K3_STAGES * STG_W * 4)     // 165888 B

__global__ __launch_bounds__(256, 1) void k3_gemm(float* __restrict__ Y) {
    extern __shared__ unsigned sh[];
    int tid = threadIdx.x, warp = tid >> 5, lane = tid & 31;
    int wm = warp >> 2, wn = warp & 3;
    int m0 = blockIdx.x * BM, n0 = blockIdx.y * BN;

    float acc[4][8][4] = {};                 // mt x (np*2+half) x 4

    unsigned* stA[K3_STAGES];
    unsigned* stB[K3_STAGES];
    #pragma unroll
    for (int s = 0; s < K3_STAGES; s++) {
        stA[s] = sh + s * STG_W;
        stB[s] = sh + s * STG_W + STG_WA;
    }

    // ldmatrix lane-relative offsets (bytes)
    int g4 = lane >> 3, lr = lane & 7;
    uint32_t relA[4], relB[4];
    {
        int rowSel = (g4 & 1) * 8 + lr;
        int wordSel = (g4 >> 1) * 4;
        #pragma unroll
        for (int mt = 0; mt < 4; mt++)
            relA[mt] = ((wm * 64 + mt * 16 + rowSel) * 36 + wordSel) * 4;
        int browSel = (g4 >> 1) * 8 + lr;
        int bwordSel = (g4 & 1) * 4;
        #pragma unroll
        for (int np = 0; np < 4; np++)
            relB[np] = ((wn * 64 + np * 16 + browSel) * 36 + bwordSel) * 4;
    }
    uint32_t uA[K3_STAGES], uB[K3_STAGES];
    #pragma unroll
    for (int s = 0; s < K3_STAGES; s++) {
        uA[s] = smem_u32(stA[s]);
        uB[s] = smem_u32(stB[s]);
    }

    auto prefetch = [&](int st, int kt) {
        unsigned* As = stA[st];
        unsigned* Bs = stB[st];
        const __half* gA = g_Dh + (size_t)m0 * KMID + kt * 64;
        const __half* gB = g_Wt + (size_t)n0 * KMID + kt * 64;
        // A: 128 rows x 8 chunks = 1024; 4 iters of 256 threads
        #pragma unroll
        for (int i = 0; i < 4; i++) {
            int j = tid + i * 256;
            int r = j >> 3, c = j & 7;
            cp16(As + r * 36 + c * 4, (const char*)(gA + (size_t)r * KMID) + c * 16);
        }
        // B: 256 rows x 8 chunks = 2048; 8 iters
        #pragma unroll
        for (int i = 0; i < 8; i++) {
            int j = tid + i * 256;
            int r = j >> 3, c = j & 7;
            cp16(Bs + r * 36 + c * 4, (const char*)(gB + (size_t)r * KMID) + c * 16);
        }
        asm volatile("cp.async.commit_group;\n" ::: "memory");
    };

    prefetch(0, 0);
    prefetch(1, 1);

    for (int kt = 0; kt < NKT; kt++) {
        int st = kt % K3_STAGES;
        if (kt + 2 < NKT) {
            prefetch((kt + 2) % K3_STAGES, kt + 2);
            asm volatile("cp.async.wait_group 2;\n" ::: "memory");
        } else if (kt + 1 < NKT) {
            asm volatile("cp.async.wait_group 1;\n" ::: "memory");
        } else {
            asm volatile("cp.async.wait_group 0;\n" ::: "memory");
        }
        __syncthreads();

        #pragma unroll
        for (int s = 0; s < 4; s++) {       // 4 x k16 per tile
            unsigned a[4][4], b[4][4];
            #pragma unroll
            for (int mt = 0; mt < 4; mt++)
                ldsm4(a[mt][0], a[mt][1], a[mt][2], a[mt][3],
                      uA[st] + relA[mt] + s * 32);
            #pragma unroll
            for (int np = 0; np < 4; np++)
                ldsm4(b[np][0], b[np][1], b[np][2], b[np][3],
                      uB[st] + relB[np] + s * 32);
            #pragma unroll
            for (int mt = 0; mt < 4; mt++) {
                #pragma unroll
                for (int np = 0; np < 4; np++) {
                    mma16(acc[mt][np * 2],     a[mt], b[np][0], b[np][1]);
                    mma16(acc[mt][np * 2 + 1], a[mt], b[np][2], b[np][3]);
                }
            }
        }
        __syncthreads();
    }

    // epilogue: scale + store
    #pragma unroll
    for (int mt = 0; mt < 4; mt++) {
        #pragma unroll
        for (int nf = 0; nf < 8; nf++) {
            int row = m0 + wm * 64 + mt * 16 + (lane >> 2);
            int col = n0 + wn * 64 + nf * 8 + 2 * (lane & 3);
            float2 v0 = make_float2(acc[mt][nf][0] * SCALING,
                                    acc[mt][nf][1] * SCALING);
            float2 v1 = make_float2(acc[mt][nf][2] * SCALING,
                                    acc[mt][nf][3] * SCALING);
            *(float2*)(Y + (size_t)row * DOUT + col)       = v0;
            *(float2*)(Y + (size_t)(row + 8) * DOUT + col) = v1;
        }
    }
}

// ---------------------------------------------------------------------------
// Launch
// ---------------------------------------------------------------------------
extern "C" void kernel_launch(void* const* d_in, const int* in_sizes, int n_in,
                              void* d_out, int out_size) {
    (void)in_sizes; (void)n_in; (void)out_size;
    const float* x       = (const float*)d_in[0];
    const float* route_w = (const float*)d_in[1];
    const float* A       = (const float*)d_in[2];
    const float* B       = (const float*)d_in[3];
    float* y = (float*)d_out;

    cudaFuncSetAttribute(k3_gemm, cudaFuncAttributeMaxDynamicSharedMemorySize,
                         K3_SMEM);

    int prep_elems = N72 * DIN + DOUT * KMID;
    k0_prep<<<(prep_elems + 255) / 256, 256>>>(route_w, A, B);
    k1_fused<<<TOKENS / 128, 256>>>(x);
    dim3 g3(TOKENS / BM, DOUT / BN);
    k3_gemm<<<g3, 256, K3_SMEM>>>(y);
}

// round 8
// speedup vs baseline: 2.8517x; 1.1660x over previous
#include <cuda_runtime.h>
#include <cuda_fp16.h>
#include <cstdint>
#include <cstddef>

// Problem constants
#define TOKENS 32768      // 8 * 4096
#define DIN    1024
#define RNK    64
#define NE     8
#define N72    72         // NE + RNK
#define DOUT   1024
#define KMID   512        // NE * RNK
#define SCALING 0.25f     // alpha / r = 16/64

// ---------------------------------------------------------------------------
// Scratch (device globals; no runtime allocation allowed)
// ---------------------------------------------------------------------------
__device__ __half g_W72h[N72 * DIN];             // [72][1024] fp16
__device__ __half g_Wt[DOUT * KMID];             // [o][k]: Wt[o][e*64+r] = B[e][o][r]
__device__ __half g_Dh[(size_t)TOKENS * KMID];   // 32 MiB: D[t][e*64+r] fp16

// ---------------------------------------------------------------------------
// Helpers
// ---------------------------------------------------------------------------
__device__ __forceinline__ void mma16(float c[4], const unsigned a[4],
                                      unsigned b0, unsigned b1) {
    asm volatile(
        "mma.sync.aligned.m16n8k16.row.col.f32.f16.f16.f32 "
        "{%0,%1,%2,%3}, {%4,%5,%6,%7}, {%8,%9}, {%0,%1,%2,%3};\n"
        : "+f"(c[0]), "+f"(c[1]), "+f"(c[2]), "+f"(c[3])
        : "r"(a[0]), "r"(a[1]), "r"(a[2]), "r"(a[3]), "r"(b0), "r"(b1));
}

__device__ __forceinline__ void cp16(void* smem, const void* gmem) {
    unsigned saddr = (unsigned)__cvta_generic_to_shared(smem);
    asm volatile("cp.async.cg.shared.global [%0], [%1], 16;\n"
                 :: "r"(saddr), "l"(gmem));
}

__device__ __forceinline__ uint32_t smem_u32(const void* p) {
    return (uint32_t)__cvta_generic_to_shared(p);
}

__device__ __forceinline__ void ldsm4(unsigned& r0, unsigned& r1,
                                      unsigned& r2, unsigned& r3,
                                      uint32_t addr) {
    asm volatile("ldmatrix.sync.aligned.m8n8.x4.shared.b16 "
                 "{%0,%1,%2,%3}, [%4];"
                 : "=r"(r0), "=r"(r1), "=r"(r2), "=r"(r3) : "r"(addr));
}

// ---------------------------------------------------------------------------
// K0: prep weights (fp16)
// ---------------------------------------------------------------------------
__global__ void k0_prep(const float* __restrict__ route_w,
                        const float* __restrict__ A,
                        const float* __restrict__ B) {
    int idx = blockIdx.x * 256 + threadIdx.x;
    if (idx < N72 * DIN) {
        int n = idx / DIN, d = idx % DIN;
        float v = (n < NE) ? route_w[n * DIN + d] : A[(n - NE) * DIN + d];
        g_W72h[idx] = __float2half_rn(v);
    }
    int j = idx - N72 * DIN;
    if (j >= 0 && j < DOUT * KMID) {
        int o = j / KMID, k = j % KMID;
        int e = k >> 6, r = k & 63;
        g_Wt[j] = __float2half_rn(B[(e * DOUT + o) * RNK + r]);
    }
}

// ---------------------------------------------------------------------------
// K1: fused router+compress (fp16 mma) -> softmax -> outer -> D (fp16)
// ---------------------------------------------------------------------------
__global__ __launch_bounds__(256) void k1_fused(const float* __restrict__ X) {
    __shared__ float shf[9728];              // 38912 B, reused for Cs
    unsigned* Xs = (unsigned*)shf;           // [128][36] words
    unsigned* Ws = (unsigned*)shf + 128 * 36;// [72][36] words

    int tid = threadIdx.x, warp = tid >> 5, lane = tid & 31;
    int m0 = blockIdx.x * 128;

    float acc[9][4] = {};

    float4 xr[8];
    uint4  wr[3];

    auto loadg = [&](int kt) {
        #pragma unroll
        for (int i = 0; i < 8; i++) {
            int idx = tid + i * 256;
            int r = idx >> 4, c4 = idx & 15;
            xr[i] = *(const float4*)(X + (size_t)(m0 + r) * DIN + kt + c4 * 4);
        }
        #pragma unroll
        for (int i = 0; i < 3; i++) {
            int idx = tid + i * 256;
            if (idx < 576) {
                int r = idx >> 3, c = idx & 7;
                wr[i] = *(const uint4*)((const char*)(g_W72h + r * DIN + kt) + c * 16);
            }
        }
    };

    loadg(0);

    for (int kt = 0; kt < 16; kt++) {
        #pragma unroll
        for (int i = 0; i < 8; i++) {
            int idx = tid + i * 256;
            int r = idx >> 4, c4 = idx & 15;
            __half2* dst = (__half2*)(Xs + r * 36 + c4 * 2);
            dst[0] = __floats2half2_rn(xr[i].x, xr[i].y);
            dst[1] = __floats2half2_rn(xr[i].z, xr[i].w);
        }
        #pragma unroll
        for (int i = 0; i < 3; i++) {
            int idx = tid + i * 256;
            if (idx < 576) {
                int r = idx >> 3, c = idx & 7;
                *(uint4*)(Ws + r * 36 + c * 4) = wr[i];
            }
        }
        __syncthreads();

        if (kt + 1 < 16) loadg((kt + 1) * 64);   // gmem loads overlap MMA below

        #pragma unroll
        for (int s = 0; s < 4; s++) {       // 4 x k16
            unsigned a[4];
            int ar = warp * 16 + (lane >> 2);
            int w = s * 8 + (lane & 3);
            a[0] = Xs[ar * 36 + w];
            a[1] = Xs[(ar + 8) * 36 + w];
            a[2] = Xs[ar * 36 + w + 4];
            a[3] = Xs[(ar + 8) * 36 + w + 4];
            #pragma unroll
            for (int j = 0; j < 9; j++) {
                int br = j * 8 + (lane >> 2);
                unsigned b0 = Ws[br * 36 + w];
                unsigned b1 = Ws[br * 36 + w + 4];
                mma16(acc[j], a, b0, b1);
            }
        }
        __syncthreads();
    }

    // stage C72 into smem: Cs[128][76]
    float* Cs = shf;
    #pragma unroll
    for (int j = 0; j < 9; j++) {
        int col = j * 8 + 2 * (lane & 3);
        int row = warp * 16 + (lane >> 2);
        Cs[row * 76 + col]           = acc[j][0];
        Cs[row * 76 + col + 1]       = acc[j][1];
        Cs[(row + 8) * 76 + col]     = acc[j][2];
        Cs[(row + 8) * 76 + col + 1] = acc[j][3];
    }
    __syncthreads();

    // softmax + outer product; 8-thread groups, 4 tokens each
    int grp = tid >> 3, g = tid & 7;
    #pragma unroll
    for (int tt = 0; tt < 4; tt++) {
        int lt = grp + tt * 32;
        const float* crow = Cs + lt * 76;
        float mx = crow[0];
        #pragma unroll
        for (int e = 1; e < 8; e++) mx = fmaxf(mx, crow[e]);
        float p[8]; float se = 0.f;
        #pragma unroll
        for (int e = 0; e < 8; e++) { p[e] = expf(crow[e] - mx); se += p[e]; }
        float inv = 1.f / se;
        __half* drow = g_Dh + (size_t)(m0 + lt) * KMID;
        #pragma unroll
        for (int e = 0; e < 8; e++) {
            float route = p[e] * inv;
            #pragma unroll
            for (int h = 0; h < 2; h++) {
                int r = (g + h * 8) * 4;
                float4 cv = *(const float4*)(crow + 8 + r);
                __half2 h0 = __floats2half2_rn(route * cv.x, route * cv.y);
                __half2 h1 = __floats2half2_rn(route * cv.z, route * cv.w);
                *(__half2*)(drow + e * 64 + r)     = h0;
                *(__half2*)(drow + e * 64 + r + 2) = h1;
            }
        }
    }
}

// ---------------------------------------------------------------------------
// K3: GEMM2: Y = (D @ Wt^T) * SCALING, fp16 mma fp32 accum.
//   M=32768 N=1024 K=512. Block 128x128, 128 threads (4 warps 2x2),
//   warp tile 64x64, K-tile 64 halves, 2-stage cp.async ring, ldmatrix.
//   2 CTAs/SM (regs ~51K, smem 147KB total) -> inter-CTA overlap.
// ---------------------------------------------------------------------------
#define BM 128
#define BN 128
#define NKT 8                               // 512 / 64
#define STG_W (2 * BM * 36)                 // A+B words per stage
#define K3_STAGES 2
#define K3_SMEM (K3_STAGES * STG_W * 4)     // 73728 B

__global__ __launch_bounds__(128, 2) void k3_gemm(float* __restrict__ Y) {
    extern __shared__ unsigned sh[];
    int tid = threadIdx.x, warp = tid >> 5, lane = tid & 31;
    int wm = warp >> 1, wn = warp & 1;
    int m0 = blockIdx.x * BM, n0 = blockIdx.y * BN;

    float acc[4][8][4] = {};                 // mt x (np*2+half) x 4

    unsigned* stA[K3_STAGES];
    unsigned* stB[K3_STAGES];
    #pragma unroll
    for (int s = 0; s < K3_STAGES; s++) {
        stA[s] = sh + s * STG_W;
        stB[s] = sh + s * STG_W + BM * 36;
    }

    // ldmatrix lane-relative offsets (bytes)
    int g4 = lane >> 3, lr = lane & 7;
    uint32_t relA[4], relB[4];
    {
        int rowSel = (g4 & 1) * 8 + lr;
        int wordSel = (g4 >> 1) * 4;
        #pragma unroll
        for (int mt = 0; mt < 4; mt++)
            relA[mt] = ((wm * 64 + mt * 16 + rowSel) * 36 + wordSel) * 4;
        int browSel = (g4 >> 1) * 8 + lr;
        int bwordSel = (g4 & 1) * 4;
        #pragma unroll
        for (int np = 0; np < 4; np++)
            relB[np] = ((wn * 64 + np * 16 + browSel) * 36 + bwordSel) * 4;
    }
    uint32_t uA[K3_STAGES], uB[K3_STAGES];
    #pragma unroll
    for (int s = 0; s < K3_STAGES; s++) {
        uA[s] = smem_u32(stA[s]);
        uB[s] = smem_u32(stB[s]);
    }

    auto prefetch = [&](int st, int kt) {
        unsigned* As = stA[st];
        unsigned* Bs = stB[st];
        const __half* gA = g_Dh + (size_t)m0 * KMID + kt * 64;
        const __half* gB = g_Wt + (size_t)n0 * KMID + kt * 64;
        // A: 128 rows x 8 chunks = 1024; 8 iters of 128 threads
        #pragma unroll
        for (int i = 0; i < 8; i++) {
            int j = tid + i * 128;
            int r = j >> 3, c = j & 7;
            cp16(As + r * 36 + c * 4, (const char*)(gA + (size_t)r * KMID) + c * 16);
        }
        #pragma unroll
        for (int i = 0; i < 8; i++) {
            int j = tid + i * 128;
            int r = j >> 3, c = j & 7;
            cp16(Bs + r * 36 + c * 4, (const char*)(gB + (size_t)r * KMID) + c * 16);
        }
        asm volatile("cp.async.commit_group;\n" ::: "memory");
    };

    prefetch(0, 0);

    for (int kt = 0; kt < NKT; kt++) {
        int st = kt & 1;
        if (kt + 1 < NKT) {
            prefetch(st ^ 1, kt + 1);
            asm volatile("cp.async.wait_group 1;\n" ::: "memory");
        } else {
            asm volatile("cp.async.wait_group 0;\n" ::: "memory");
        }
        __syncthreads();

        #pragma unroll
        for (int s = 0; s < 4; s++) {       // 4 x k16 per tile
            unsigned a[4][4], b[4][4];
            #pragma unroll
            for (int mt = 0; mt < 4; mt++)
                ldsm4(a[mt][0], a[mt][1], a[mt][2], a[mt][3],
                      uA[st] + relA[mt] + s * 32);
            #pragma unroll
            for (int np = 0; np < 4; np++)
                ldsm4(b[np][0], b[np][1], b[np][2], b[np][3],
                      uB[st] + relB[np] + s * 32);
            #pragma unroll
            for (int mt = 0; mt < 4; mt++) {
                #pragma unroll
                for (int np = 0; np < 4; np++) {
                    mma16(acc[mt][np * 2],     a[mt], b[np][0], b[np][1]);
                    mma16(acc[mt][np * 2 + 1], a[mt], b[np][2], b[np][3]);
                }
            }
        }
        __syncthreads();
    }

    // epilogue: scale + store
    #pragma unroll
    for (int mt = 0; mt < 4; mt++) {
        #pragma unroll
        for (int nf = 0; nf < 8; nf++) {
            int row = m0 + wm * 64 + mt * 16 + (lane >> 2);
            int col = n0 + wn * 64 + nf * 8 + 2 * (lane & 3);
            float2 v0 = make_float2(acc[mt][nf][0] * SCALING,
                                    acc[mt][nf][1] * SCALING);
            float2 v1 = make_float2(acc[mt][nf][2] * SCALING,
                                    acc[mt][nf][3] * SCALING);
            *(float2*)(Y + (size_t)row * DOUT + col)       = v0;
            *(float2*)(Y + (size_t)(row + 8) * DOUT + col) = v1;
        }
    }
}

// ---------------------------------------------------------------------------
// Launch
// ---------------------------------------------------------------------------
extern "C" void kernel_launch(void* const* d_in, const int* in_sizes, int n_in,
                              void* d_out, int out_size) {
    (void)in_sizes; (void)n_in; (void)out_size;
    const float* x       = (const float*)d_in[0];
    const float* route_w = (const float*)d_in[1];
    const float* A       = (const float*)d_in[2];
    const float* B       = (const float*)d_in[3];
    float* y = (float*)d_out;

    cudaFuncSetAttribute(k3_gemm, cudaFuncAttributeMaxDynamicSharedMemorySize,
                         K3_SMEM);

    int prep_elems = N72 * DIN + DOUT * KMID;
    k0_prep<<<(prep_elems + 255) / 256, 256>>>(route_w, A, B);
    k1_fused<<<TOKENS / 128, 256>>>(x);
    dim3 g3(TOKENS / BM, DOUT / BN);
    k3_gemm<<<g3, 128, K3_SMEM>>>(y);
}